// round 6
// baseline (speedup 1.0000x reference)
#include <cuda_runtime.h>
#include <math.h>
#include <stdint.h>

#define NPATH 11

// ---------------------------------------------------------------------------
// device globals (no allocation allowed)
// ---------------------------------------------------------------------------
__device__ float g_hctp_cg[NPATH * 125];            // compact [p][(m1*d2+m2)*d3+k]

// ---------------------------------------------------------------------------
// CG builder (fp64, replicates numpy pipeline; l=2 basis analytic from LAPACK)
// VERIFIED correct (rel_err ~1e-6) — do not touch.
// ---------------------------------------------------------------------------
__device__ __forceinline__ double d_fact(int n){ double f=1; for(int i=2;i<=n;i++) f*=i; return f; }
__device__ __forceinline__ double d_dfact(int n){ double o=1; for(int k=n;k>0;k-=2) o*=k; return o; }
__device__ __forceinline__ double d_gmom(int n){ return (n&1) ? 0.0 : d_dfact(n-1); }
__device__ __forceinline__ int d_cidx(int L,int a,int b){ int t=L-a; return t*(t+1)/2 + (t-b); }

__device__ __forceinline__ double d_getB(int l, int i, int m, const double B2[6][5]){
    if (l==0) return 1.0;
    if (l==1) return (i==m) ? 1.0 : 0.0;
    return B2[i][m];
}

__global__ void hctp_build_cg(){
    __shared__ double sGL[NPATH][15][15];
    __shared__ double sV [NPATH][15][5];
    __shared__ double sR [NPATH][5][15];
    __shared__ double sG [NPATH][5][5];

    const int t = threadIdx.x;
    if (t >= NPATH) return;

    const int L1t[NPATH]={0,0,0,1,1,1,1,2,2,2,2};
    const int L2t[NPATH]={0,1,2,0,1,1,2,0,1,2,2};
    const int L3t[NPATH]={0,1,2,1,0,2,1,2,1,0,2};
    const int l1=L1t[t], l2=L2t[t], l3=L3t[t];
    const int L = l1 + l2;
    const int DL = (L+1)*(L+2)/2;
    const int d1 = 2*l1+1, d2 = 2*l2+1, d3 = 2*l3+1;

    double B2[6][5];
    for (int i=0;i<6;i++) for (int m=0;m<5;m++) B2[i][m]=0.0;
    {
        double s3 = sqrt(3.0), s2 = sqrt(2.0), s6 = sqrt(6.0);
        double pp = (3.0+s3)/(6.0*s2);
        double qq = (3.0-s3)/(6.0*s2);
        double rr = 1.0/s6;
        B2[1][0]=1.0;  B2[2][1]=1.0;  B2[4][3]=1.0;
        B2[0][2]=-rr;  B2[3][2]= pp;  B2[5][2]=-qq;
        B2[0][4]=-rr;  B2[3][4]=-qq;  B2[5][4]= pp;
    }

    int ca[15], cb[15];
    { int n=0; for(int a=L;a>=0;a--) for(int b=L-a;b>=0;b--){ ca[n]=a; cb[n]=b; n++; } }

    for (int i=0;i<DL;i++) for (int j=0;j<DL;j++){
        int aa = ca[i]+ca[j], bb = cb[i]+cb[j];
        int cc = (L-ca[i]-cb[i]) + (L-ca[j]-cb[j]);
        sGL[t][i][j] = d_gmom(aa)*d_gmom(bb)*d_gmom(cc);
    }

    const int kr = (L - l3)/2;
    const int Dl = (l3+1)*(l3+2)/2;
    int la[6], lb[6];
    { int n=0; for(int a=l3;a>=0;a--) for(int b=l3-a;b>=0;b--){ la[n]=a; lb[n]=b; n++; } }
    for (int i=0;i<DL;i++) for (int m=0;m<d3;m++) sV[t][i][m]=0.0;
    for (int j=0;j<Dl;j++){
        for (int p=0;p<=kr;p++) for (int q=0;q<=kr-p;q++){
            int r = kr - p - q;
            double coef = d_fact(kr)/(d_fact(p)*d_fact(q)*d_fact(r));
            int row = d_cidx(L, la[j]+2*p, lb[j]+2*q);
            for (int m=0;m<d3;m++) sV[t][row][m] += coef * d_getB(l3, j, m, B2);
        }
    }

    for (int m=0;m<d3;m++) for (int c=0;c<DL;c++){
        double s=0; for (int u=0;u<DL;u++) s += sV[t][u][m]*sGL[t][u][c];
        sR[t][m][c]=s;
    }
    for (int m=0;m<d3;m++) for (int m2=0;m2<d3;m2++){
        double s=0; for (int c=0;c<DL;c++) s += sR[t][m][c]*sV[t][c][m2];
        sG[t][m][m2]=s;
    }

    for (int c=0;c<d3;c++){
        int piv=c; double mx=fabs(sG[t][c][c]);
        for (int r=c+1;r<d3;r++){ double v=fabs(sG[t][r][c]); if (v>mx){mx=v;piv=r;} }
        if (piv!=c){
            for (int q=0;q<d3;q++){ double tmp=sG[t][c][q]; sG[t][c][q]=sG[t][piv][q]; sG[t][piv][q]=tmp; }
            for (int q=0;q<DL;q++){ double tmp=sR[t][c][q]; sR[t][c][q]=sR[t][piv][q]; sR[t][piv][q]=tmp; }
        }
        double inv = 1.0/sG[t][c][c];
        for (int q=0;q<d3;q++) sG[t][c][q]*=inv;
        for (int q=0;q<DL;q++) sR[t][c][q]*=inv;
        for (int r=0;r<d3;r++){
            if (r==c) continue;
            double f = sG[t][r][c];
            if (f==0.0) continue;
            for (int q=0;q<d3;q++) sG[t][r][q] -= f*sG[t][c][q];
            for (int q=0;q<DL;q++) sR[t][r][q] -= f*sR[t][c][q];
        }
    }

    const int D1cnt = (l1+1)*(l1+2)/2;
    const int D2cnt = (l2+1)*(l2+2)/2;
    int a1s[6], b1s[6], a2s[6], b2s[6];
    { int n=0; for(int a=l1;a>=0;a--) for(int b=l1-a;b>=0;b--){ a1s[n]=a; b1s[n]=b; n++; } }
    { int n=0; for(int a=l2;a>=0;a--) for(int b=l2-a;b>=0;b--){ a2s[n]=a; b2s[n]=b; n++; } }

    for (int m1=0;m1<d1;m1++){
        for (int m2=0;m2<d2;m2++){
            double tL[15];
            for (int q=0;q<DL;q++) tL[q]=0.0;
            for (int i1=0;i1<D1cnt;i1++){
                double bv1 = d_getB(l1, i1, m1, B2);
                if (bv1==0.0) continue;
                for (int i2=0;i2<D2cnt;i2++){
                    double bv2 = d_getB(l2, i2, m2, B2);
                    if (bv2==0.0) continue;
                    int row = d_cidx(L, a1s[i1]+a2s[i2], b1s[i1]+b2s[i2]);
                    tL[row] += bv1*bv2;
                }
            }
            for (int k=0;k<d3;k++){
                double s=0;
                for (int c=0;c<DL;c++) s += sR[t][k][c]*tL[c];
                g_hctp_cg[t*125 + (m1*d2+m2)*d3 + k] = (float)s;
            }
        }
    }
}

// ---------------------------------------------------------------------------
// zero output
// ---------------------------------------------------------------------------
__global__ void hctp_zero(float* __restrict__ out, size_t n){
    size_t i = (size_t)blockIdx.x * blockDim.x + threadIdx.x;
    size_t stride = (size_t)gridDim.x * blockDim.x;
    for (; i < n; i += stride) out[i] = 0.f;
}

// ---------------------------------------------------------------------------
// main per-path kernel — j-paired f32x2 rank-update, LDS.128 operand loads
// ---------------------------------------------------------------------------
constexpr int tp_smem_floats(int l1,int l2,int l3){
    int d1=2*l1+1, d2=2*l2+1, d3=2*l3+1;
    return 16*(64*d1+1) + 16*(64*d2+1) + 64*68 + d3*16*68 + d1*d2*d3;
}

__device__ __forceinline__ void ffma2(unsigned long long& acc,
                                      unsigned long long a,
                                      unsigned long long b){
    asm("fma.rn.f32x2 %0, %1, %2, %0;" : "+l"(acc) : "l"(a), "l"(b));
}

template<int L1,int L2,int L3,int P>
__global__ void __launch_bounds__(256,2) tp_kernel(
    const float* __restrict__ x1, const float* __restrict__ x2,
    const float* __restrict__ w,  float* __restrict__ out, int n)
{
    constexpr int D1=2*L1+1, D2=2*L2+1, D3=2*L3+1;
    constexpr int K0 = (L3==0)?0:((L3==1)?1:4);
    constexpr int NB=16;
    constexpr int S1 = 64*D1+1, S2 = 64*D2+1;
    constexpr int CH1 = 64*D1, CH2 = 64*D2;
    constexpr int WST = 68;                 // sW row stride ([o][j]) — 272B, 16B-aligned
    constexpr int ZST = 68;                 // sZ row stride ([k*16+b][j])

    extern __shared__ float sm[];
    float* sX1 = sm;                        // NB*S1
    float* sX2 = sX1 + NB*S1;               // NB*S2
    float* sW  = sX2 + NB*S2;               // 64*WST
    float* sZ  = sW + 64*WST;               // D3*16*ZST
    float* sCG = sZ + D3*16*ZST;            // D1*D2*D3

    const int t = threadIdx.x;
    const int B0 = blockIdx.x * NB;

    for (int q=t; q<D1*D2*D3; q+=256) sCG[q] = g_hctp_cg[P*125+q];
    for (int q=t; q<NB*CH1; q+=256){
        int b = q / CH1, rem = q - b*CH1;
        sX1[b*S1 + rem] = (B0+b < n) ? x1[(size_t)(B0+b)*CH1 + rem] : 0.f;
    }
    for (int q=t; q<NB*CH2; q+=256){
        int b = q / CH2, rem = q - b*CH2;
        sX2[b*S2 + rem] = (B0+b < n) ? x2[(size_t)(B0+b)*CH2 + rem] : 0.f;
    }
    __syncthreads();

    // FMA-phase mapping: lanes 0-15 (og) pick o = og + 16*oo; w LDS.128 is
    // quad-phase conflict-free at stride 68; z LDS.128 broadcasts per half-warp.
    const int lane = t & 31, wrp = t >> 5;
    const int og = lane & 15;
    const int bF = wrp*2 + (lane>>4);
    // Z-phase mapping
    const int bZ = t & 15, jg = t >> 4;

    const float* wp = w + ((size_t)P << 18);

    unsigned long long acc2[4][D3];
    #pragma unroll
    for (int oo=0;oo<4;oo++)
        #pragma unroll
        for (int k=0;k<D3;k++) acc2[oo][k]=0ull;

    for (int i=0;i<64;i++){
        __syncthreads();  // prev FMA readers of sW/sZ done

        // prefetch this i's w tile into registers (L2 latency hidden by z-phase)
        float4 wreg[4];
        #pragma unroll
        for (int s=0;s<4;s++){
            int q = t + s*256;                    // 0..1023
            int o = q >> 4, j4 = (q & 15) << 2;
            wreg[s] = *(const float4*)(wp + (size_t)o*4096 + i*64 + j4);
        }

        // z phase: t[n][k] = sum_m x1[bZ,i,m]*CG[m,n,k]; z = t . x2
        {
            float a_[D1];
            #pragma unroll
            for (int m=0;m<D1;m++) a_[m] = sX1[bZ*S1 + i*D1 + m];
            float tt[D2][D3];
            #pragma unroll
            for (int nn=0;nn<D2;nn++)
                #pragma unroll
                for (int k=0;k<D3;k++) tt[nn][k]=0.f;
            #pragma unroll
            for (int m=0;m<D1;m++)
                #pragma unroll
                for (int nn=0;nn<D2;nn++)
                    #pragma unroll
                    for (int k=0;k<D3;k++){
                        float c = sCG[(m*D2+nn)*D3+k];
                        tt[nn][k] += c*a_[m];
                    }
            #pragma unroll
            for (int jj=0;jj<4;jj++){
                int j = jg*4+jj;
                float xv[D2];
                #pragma unroll
                for (int nn=0;nn<D2;nn++) xv[nn] = sX2[bZ*S2 + j*D2 + nn];
                #pragma unroll
                for (int k=0;k<D3;k++){
                    float z=0.f;
                    #pragma unroll
                    for (int nn=0;nn<D2;nn++) z += tt[nn][k]*xv[nn];
                    sZ[(k*16 + bZ)*ZST + j] = z;
                }
            }
        }

        // store w tile: sW[o][j], stride 68, STS.128
        #pragma unroll
        for (int s=0;s<4;s++){
            int q = t + s*256;
            int o = q >> 4, j4 = (q & 15) << 2;
            *(float4*)(sW + o*WST + j4) = wreg[s];
        }
        __syncthreads();

        // FMA phase: rank-64 update; per jq handle 4 j via LDS.128 (= 2 f32x2)
        const float* zb = sZ + bF*ZST;
        #pragma unroll 4
        for (int jq=0;jq<16;jq++){
            ulonglong2 wv[4], zv[D3];
            #pragma unroll
            for (int oo=0;oo<4;oo++)
                wv[oo] = *(const ulonglong2*)(sW + (og+16*oo)*WST + 4*jq);
            #pragma unroll
            for (int k=0;k<D3;k++)
                zv[k] = *(const ulonglong2*)(zb + (k<<4)*ZST + 4*jq);
            #pragma unroll
            for (int oo=0;oo<4;oo++)
                #pragma unroll
                for (int k=0;k<D3;k++){
                    ffma2(acc2[oo][k], wv[oo].x, zv[k].x);
                    ffma2(acc2[oo][k], wv[oo].y, zv[k].y);
                }
        }
    }

    if (B0+bF < n){
        float* ob = out + (size_t)(B0+bF)*576 + K0;
        #pragma unroll
        for (int oo=0;oo<4;oo++){
            int o = og + 16*oo;
            #pragma unroll
            for (int k=0;k<D3;k++){
                unsigned long long v = acc2[oo][k];
                float lo = __uint_as_float((unsigned int)v);
                float hi = __uint_as_float((unsigned int)(v >> 32));
                ob[o*9 + k] += lo + hi;
            }
        }
    }
}

// ---------------------------------------------------------------------------
// launch — operand identification is SIZE-BASED (metadata order interleaves
// x1_l0, x2_l0, x1_l1, x2_l1, x1_l2, x2_l2, weight).
// ---------------------------------------------------------------------------
extern "C" void kernel_launch(void* const* d_in, const int* in_sizes, int n_in,
                              void* d_out, int out_size){
    const long long WELEMS = (long long)NPATH * 64 * 64 * 64;  // 2,883,584

    const float* w = nullptr;
    long long minOther = 0x7fffffffffffLL;
    for (int i = 0; i < n_in; i++){
        if ((long long)in_sizes[i] == WELEMS && w == nullptr) { w = (const float*)d_in[i]; }
    }
    for (int i = 0; i < n_in; i++){
        if ((const float*)d_in[i] == w) continue;
        if ((long long)in_sizes[i] < minOther) minOther = in_sizes[i];
    }
    const int nvec = (int)(minOther / 64);   // N  (l0 input is N*64*1)

    const float* x1p[3] = {nullptr,nullptr,nullptr};
    const float* x2p[3] = {nullptr,nullptr,nullptr};
    for (int i = 0; i < n_in; i++){
        const float* ptr = (const float*)d_in[i];
        if (ptr == w) continue;
        long long sz = in_sizes[i];
        for (int l = 0; l < 3; l++){
            if (sz == (long long)nvec * 64 * (2*l+1)){
                if (!x1p[l]) x1p[l] = ptr; else x2p[l] = ptr;
                break;
            }
        }
    }

    float* out = (float*)d_out;
    const int nb = (nvec + 15) / 16;

    hctp_build_cg<<<1, 32>>>();
    hctp_zero<<<1024, 256>>>(out, (size_t)nvec*576);

#define LAUNCH_PATH(Pp,L1,L2,L3) do { \
    constexpr int smem = tp_smem_floats(L1,L2,L3) * 4; \
    cudaFuncSetAttribute(tp_kernel<L1,L2,L3,Pp>, cudaFuncAttributeMaxDynamicSharedMemorySize, smem); \
    tp_kernel<L1,L2,L3,Pp><<<nb, 256, smem>>>(x1p[L1], x2p[L2], w, out, nvec); \
} while(0)

    LAUNCH_PATH(0, 0,0,0);
    LAUNCH_PATH(1, 0,1,1);
    LAUNCH_PATH(2, 0,2,2);
    LAUNCH_PATH(3, 1,0,1);
    LAUNCH_PATH(4, 1,1,0);
    LAUNCH_PATH(5, 1,1,2);
    LAUNCH_PATH(6, 1,2,1);
    LAUNCH_PATH(7, 2,0,2);
    LAUNCH_PATH(8, 2,1,1);
    LAUNCH_PATH(9, 2,2,0);
    LAUNCH_PATH(10,2,2,2);
#undef LAUNCH_PATH
}

// round 11
// speedup vs baseline: 1.4783x; 1.4783x over previous
#include <cuda_runtime.h>
#include <math.h>
#include <stdint.h>
#define NPATH 11
__device__ float g_hctp_cg[NPATH*125];

// ---------------- helpers ----------------
__device__ __forceinline__ uint32_t f2tf(float f){
    uint32_t u; asm("cvt.rna.tf32.f32 %0, %1;" : "=r"(u) : "f"(f)); return u;
}
__device__ __forceinline__ void mma8(float* d, const uint32_t* a, const uint32_t* b){
    asm volatile("mma.sync.aligned.m16n8k8.row.col.f32.tf32.tf32.f32 "
        "{%0,%1,%2,%3},{%4,%5,%6,%7},{%8,%9},{%0,%1,%2,%3};\n"
        : "+f"(d[0]),"+f"(d[1]),"+f"(d[2]),"+f"(d[3])
        : "r"(a[0]),"r"(a[1]),"r"(a[2]),"r"(a[3]),"r"(b[0]),"r"(b[1]));
}

// ---------------- CG builder (fp64, VERIFIED rel_err ~1e-6) ----------------
__device__ __forceinline__ double d_fact(int n){ double f=1; for(int i=2;i<=n;i++) f*=i; return f; }
__device__ __forceinline__ double d_dfact(int n){ double o=1; for(int k=n;k>0;k-=2) o*=k; return o; }
__device__ __forceinline__ double d_gmom(int n){ return (n&1)?0.0:d_dfact(n-1); }
__device__ __forceinline__ int d_cidx(int L,int a,int b){ int t=L-a; return t*(t+1)/2+(t-b); }
__device__ __forceinline__ double d_getB(int l,int i,int m,const double B2[6][5]){
    if(l==0) return 1.0; if(l==1) return (i==m)?1.0:0.0; return B2[i][m]; }

__global__ void hctp_build_cg(){
    __shared__ double sGL[NPATH][15][15]; __shared__ double sV[NPATH][15][5];
    __shared__ double sR[NPATH][5][15];  __shared__ double sG[NPATH][5][5];
    const int t=threadIdx.x; if(t>=NPATH) return;
    const int L1t[NPATH]={0,0,0,1,1,1,1,2,2,2,2};
    const int L2t[NPATH]={0,1,2,0,1,1,2,0,1,2,2};
    const int L3t[NPATH]={0,1,2,1,0,2,1,2,1,0,2};
    const int l1=L1t[t],l2=L2t[t],l3=L3t[t];
    const int L=l1+l2, DL=(L+1)*(L+2)/2, d1=2*l1+1, d2=2*l2+1, d3=2*l3+1;
    double B2[6][5];
    for(int i=0;i<6;i++) for(int m=0;m<5;m++) B2[i][m]=0.0;
    { double s3=sqrt(3.0),s2=sqrt(2.0),s6=sqrt(6.0);
      double pp=(3.0+s3)/(6.0*s2), qq=(3.0-s3)/(6.0*s2), rr=1.0/s6;
      B2[1][0]=1.0; B2[2][1]=1.0; B2[4][3]=1.0;
      B2[0][2]=-rr; B2[3][2]=pp;  B2[5][2]=-qq;
      B2[0][4]=-rr; B2[3][4]=-qq; B2[5][4]=pp; }
    int ca[15],cb[15];
    { int n=0; for(int a=L;a>=0;a--) for(int b=L-a;b>=0;b--){ca[n]=a;cb[n]=b;n++;} }
    for(int i=0;i<DL;i++) for(int j=0;j<DL;j++){
        int aa=ca[i]+ca[j], bb=cb[i]+cb[j];
        int cc=(L-ca[i]-cb[i])+(L-ca[j]-cb[j]);
        sGL[t][i][j]=d_gmom(aa)*d_gmom(bb)*d_gmom(cc); }
    const int kr=(L-l3)/2, Dl=(l3+1)*(l3+2)/2;
    int la[6],lb[6];
    { int n=0; for(int a=l3;a>=0;a--) for(int b=l3-a;b>=0;b--){la[n]=a;lb[n]=b;n++;} }
    for(int i=0;i<DL;i++) for(int m=0;m<d3;m++) sV[t][i][m]=0.0;
    for(int j=0;j<Dl;j++) for(int p=0;p<=kr;p++) for(int q=0;q<=kr-p;q++){
        int r=kr-p-q; double coef=d_fact(kr)/(d_fact(p)*d_fact(q)*d_fact(r));
        int row=d_cidx(L,la[j]+2*p,lb[j]+2*q);
        for(int m=0;m<d3;m++) sV[t][row][m]+=coef*d_getB(l3,j,m,B2); }
    for(int m=0;m<d3;m++) for(int c=0;c<DL;c++){
        double s=0; for(int u=0;u<DL;u++) s+=sV[t][u][m]*sGL[t][u][c]; sR[t][m][c]=s; }
    for(int m=0;m<d3;m++) for(int m2=0;m2<d3;m2++){
        double s=0; for(int c=0;c<DL;c++) s+=sR[t][m][c]*sV[t][c][m2]; sG[t][m][m2]=s; }
    for(int c=0;c<d3;c++){
        int piv=c; double mx=fabs(sG[t][c][c]);
        for(int r=c+1;r<d3;r++){ double v=fabs(sG[t][r][c]); if(v>mx){mx=v;piv=r;} }
        if(piv!=c){ for(int q=0;q<d3;q++){double tp=sG[t][c][q];sG[t][c][q]=sG[t][piv][q];sG[t][piv][q]=tp;}
                    for(int q=0;q<DL;q++){double tp=sR[t][c][q];sR[t][c][q]=sR[t][piv][q];sR[t][piv][q]=tp;} }
        double inv=1.0/sG[t][c][c];
        for(int q=0;q<d3;q++) sG[t][c][q]*=inv;
        for(int q=0;q<DL;q++) sR[t][c][q]*=inv;
        for(int r=0;r<d3;r++){ if(r==c) continue; double f=sG[t][r][c]; if(f==0.0) continue;
            for(int q=0;q<d3;q++) sG[t][r][q]-=f*sG[t][c][q];
            for(int q=0;q<DL;q++) sR[t][r][q]-=f*sR[t][c][q]; } }
    const int D1c=(l1+1)*(l1+2)/2, D2c=(l2+1)*(l2+2)/2;
    int a1s[6],b1s[6],a2s[6],b2s[6];
    { int n=0; for(int a=l1;a>=0;a--) for(int b=l1-a;b>=0;b--){a1s[n]=a;b1s[n]=b;n++;} }
    { int n=0; for(int a=l2;a>=0;a--) for(int b=l2-a;b>=0;b--){a2s[n]=a;b2s[n]=b;n++;} }
    for(int m1=0;m1<d1;m1++) for(int m2=0;m2<d2;m2++){
        double tL[15]; for(int q=0;q<DL;q++) tL[q]=0.0;
        for(int i1=0;i1<D1c;i1++){ double bv1=d_getB(l1,i1,m1,B2); if(bv1==0.0) continue;
            for(int i2=0;i2<D2c;i2++){ double bv2=d_getB(l2,i2,m2,B2); if(bv2==0.0) continue;
                tL[d_cidx(L,a1s[i1]+a2s[i2],b1s[i1]+b2s[i2])]+=bv1*bv2; } }
        for(int k=0;k<d3;k++){ double s=0; for(int c=0;c<DL;c++) s+=sR[t][k][c]*tL[c];
            g_hctp_cg[t*125+(m1*d2+m2)*d3+k]=(float)s; } }
}

// ---------------- main per-path kernel: mma.sync tf32 ----------------
__host__ __device__ constexpr int cM(int NB,int D3){ return ((NB*D3+31)/32)*32; }
__host__ __device__ constexpr int smem_floats(int l1,int l2,int l3,int nb){
    int d1=2*l1+1, d2=2*l2+1, d3=2*l3+1;
    int M=cM(nb,d3);
    return M*68 + 64*68 + nb*64*d1 + nb*64*d2 + d1*d2*d3;
}

template<int L1,int L2,int L3,int P,int NB,bool ACC>
__global__ void __launch_bounds__(256,1) tp_mma(
    const float* __restrict__ x1, const float* __restrict__ x2,
    const float* __restrict__ w,  float* __restrict__ out, int n)
{
    constexpr int D1=2*L1+1, D2=2*L2+1, D3=2*L3+1;
    constexpr int K0=(L3==0)?0:((L3==1)?1:4);
    constexpr int M = cM(NB,D3);
    constexpr int NBD3 = NB*D3;
    constexpr int CH1=64*D1, CH2=64*D2;
    constexpr int NWM = M/32, NWN = 8/NWM, NS = 64/NWN, NT = NS/8;
    constexpr int TPR = 256/M, JC = 64/TPR;
    constexpr int OZ=0, OW=M*68, OX1=OW+64*68;
    constexpr int OX2=OX1+NB*CH1, OCG=OX2+NB*D2*64;

    extern __shared__ float sm[];
    const int t=threadIdx.x;
    const int B0=blockIdx.x*NB;

    for(int q=t;q<D1*D2*D3;q+=256) sm[OCG+q]=g_hctp_cg[P*125+q];
    for(int q=t;q<NB*CH1;q+=256){ int b=q/CH1, r=q-b*CH1;
        sm[OX1+q]=(B0+b<n)?x1[(size_t)(B0+b)*CH1+r]:0.f; }
    for(int q=t;q<NB*D2*64;q+=256){ int b=q/(D2*64), r=q-b*(D2*64), nn=r>>6, j=r&63;
        sm[OX2+q]=(B0+b<n)?x2[(size_t)(B0+b)*CH2+j*D2+nn]:0.f; }

    const int lane=t&31, wid=t>>5;
    const int g=lane>>2, tid=lane&3;
    const int mw = wid % NWM, nw = wid / NWM;

    // producer mapping
    const int prow = t / TPR, ppart = t % TPR;
    const int pb = prow / D3, pk = prow - pb*D3;
    const bool pvalid = prow < NBD3;

    const float* wp = w + ((size_t)P<<18);
    float acc[2][NT][4];
    for(int a=0;a<2;a++)
        for(int b=0;b<NT;b++)
            for(int c=0;c<4;c++) acc[a][b][c]=0.f;

    for(int i=0;i<64;i++){
        __syncthreads();   // mma readers of prev i done

        // stage w tile -> sW[o][j] (tf32-rounded), o=t>>2, j quarter=(t&3)*16
        {
            const float* wr = wp + (size_t)(t>>2)*4096 + i*64 + (t&3)*16;
            float* dst = sm + OW + (t>>2)*68 + (t&3)*16;
            #pragma unroll
            for(int c=0;c<4;c++){
                float4 v=*(const float4*)(wr + c*4);
                uint4 u; u.x=f2tf(v.x); u.y=f2tf(v.y); u.z=f2tf(v.z); u.w=f2tf(v.w);
                *(uint4*)(dst + c*4) = u;
            }
        }
        // produce z rows (tf32-rounded)
        {
            float* zr = sm + OZ + prow*68 + ppart*JC;
            if(pvalid){
                float a_[D1];
                #pragma unroll
                for(int m=0;m<D1;m++) a_[m]=sm[OX1 + pb*CH1 + i*D1 + m];
                float tt[D2];
                #pragma unroll
                for(int nn=0;nn<D2;nn++){ float s_=0.f;
                    #pragma unroll
                    for(int m=0;m<D1;m++) s_+=a_[m]*sm[OCG+(m*D2+nn)*D3+pk];
                    tt[nn]=s_; }
                const float* x2b = sm + OX2 + pb*(D2*64) + ppart*JC;
                #pragma unroll
                for(int c=0;c<JC/4;c++){
                    float4 z4=make_float4(0.f,0.f,0.f,0.f);
                    #pragma unroll
                    for(int nn=0;nn<D2;nn++){
                        float4 xv=*(const float4*)(x2b + nn*64 + c*4);
                        z4.x+=tt[nn]*xv.x; z4.y+=tt[nn]*xv.y;
                        z4.z+=tt[nn]*xv.z; z4.w+=tt[nn]*xv.w;
                    }
                    uint4 u; u.x=f2tf(z4.x); u.y=f2tf(z4.y); u.z=f2tf(z4.z); u.w=f2tf(z4.w);
                    *(uint4*)(zr + c*4) = u;
                }
            } else {
                uint4 zz=make_uint4(0,0,0,0);
                #pragma unroll
                for(int c=0;c<JC/4;c++) *(uint4*)(zr + c*4) = zz;
            }
        }
        __syncthreads();

        // mma phase
        const uint32_t* zu = (const uint32_t*)(sm + OZ);
        const uint32_t* wu = (const uint32_t*)(sm + OW);
        #pragma unroll
        for(int s=0;s<8;s++){
            uint32_t afr[2][4];
            #pragma unroll
            for(int mt=0;mt<2;mt++){
                int r0 = mw*32 + mt*16 + g;
                const uint32_t* z0 = zu + r0*68 + s*8 + tid;
                const uint32_t* z1 = zu + (r0+8)*68 + s*8 + tid;
                afr[mt][0]=z0[0]; afr[mt][1]=z1[0]; afr[mt][2]=z0[4]; afr[mt][3]=z1[4];
            }
            uint32_t bfr[NT][2];
            #pragma unroll
            for(int nt=0;nt<NT;nt++){
                int o = nw*NS + nt*8 + g;
                const uint32_t* wr = wu + o*68 + s*8 + tid;
                bfr[nt][0]=wr[0]; bfr[nt][1]=wr[4];
            }
            #pragma unroll
            for(int mt=0;mt<2;mt++)
                #pragma unroll
                for(int nt=0;nt<NT;nt++)
                    mma8(acc[mt][nt], afr[mt], bfr[nt]);
        }
    }

    // epilogue: registers -> global
    #pragma unroll
    for(int mt=0;mt<2;mt++){
        #pragma unroll
        for(int rr=0;rr<2;rr++){
            int row = mw*32 + mt*16 + g + rr*8;
            if(row >= NBD3) continue;
            int b = row / D3, k = row - (row/D3)*D3;
            if(B0+b >= n) continue;
            float* ob = out + (size_t)(B0+b)*576 + K0 + k;
            #pragma unroll
            for(int nt=0;nt<NT;nt++){
                int o = nw*NS + nt*8 + 2*tid;
                float v0 = acc[mt][nt][rr*2+0];
                float v1 = acc[mt][nt][rr*2+1];
                if(ACC){ ob[o*9]+=v0; ob[(o+1)*9]+=v1; }
                else   { ob[o*9]=v0;  ob[(o+1)*9]=v1;  }
            }
        }
    }
}

// ---------------- launch (size-based operand identification) ----------------
extern "C" void kernel_launch(void* const* d_in, const int* in_sizes, int n_in,
                              void* d_out, int out_size){
    const long long WELEMS=(long long)NPATH*64*64*64;
    const float* w=nullptr;
    long long minOther=0x7fffffffffffLL;
    for(int i=0;i<n_in;i++) if((long long)in_sizes[i]==WELEMS && !w) w=(const float*)d_in[i];
    for(int i=0;i<n_in;i++){ if((const float*)d_in[i]==w) continue;
        if((long long)in_sizes[i]<minOther) minOther=in_sizes[i]; }
    const int nvec=(int)(minOther/64);
    const float* x1p[3]={nullptr,nullptr,nullptr};
    const float* x2p[3]={nullptr,nullptr,nullptr};
    for(int i=0;i<n_in;i++){
        const float* p=(const float*)d_in[i]; if(p==w) continue;
        long long sz=in_sizes[i];
        for(int l=0;l<3;l++) if(sz==(long long)nvec*64*(2*l+1)){
            if(!x1p[l]) x1p[l]=p; else x2p[l]=p; break; }
    }
    float* out=(float*)d_out;

    hctp_build_cg<<<1,32>>>();

#define LP(Pp,L1,L2,L3,NB,ACC) do{ \
    constexpr int smem=smem_floats(L1,L2,L3,NB)*4; \
    cudaFuncSetAttribute(tp_mma<L1,L2,L3,Pp,NB,ACC>, cudaFuncAttributeMaxDynamicSharedMemorySize, smem); \
    tp_mma<L1,L2,L3,Pp,NB,ACC><<<(nvec+NB-1)/NB,256,smem>>>(x1p[L1],x2p[L2],w,out,nvec); }while(0)

    LP(0, 0,0,0, 48, false);
    LP(1, 0,1,1, 42, false);
    LP(2, 0,2,2, 25, false);
    LP(3, 1,0,1, 42, true);
    LP(4, 1,1,0, 48, true);
    LP(5, 1,1,2, 25, true);
    LP(6, 1,2,1, 42, true);
    LP(7, 2,0,2, 25, true);
    LP(8, 2,1,1, 42, true);
    LP(9, 2,2,0, 48, true);
    LP(10,2,2,2, 25, true);
#undef LP
}